// round 4
// baseline (speedup 1.0000x reference)
#include <cuda_runtime.h>

#define NN 50000
#define EE 800000
#define CC 128
#define CV 32            // CC/4 float4 per row
#define CAP 128          // deg ~ Poisson(16), max ~50 << 128

// ---------------- scratch (device globals; no allocation allowed) -----------
__device__ int    g_cnt[NN];          // edge in-degree (== fill cursor)
__device__ float4 g_h[NN * CV];       // h' = dinv * (x @ W_gcn)   (25.6 MB)
__device__ int    g_bucket[NN * CAP]; // src ids grouped by dst    (25.6 MB)

// ---------------- bucket build ------------------------------------------------
__global__ void k_init() {
    int i = blockIdx.x * blockDim.x + threadIdx.x;
    if (i < NN) g_cnt[i] = 0;
}

__global__ void k_fill(const int* __restrict__ ei) {
    int e = blockIdx.x * blockDim.x + threadIdx.x;
    if (e >= EE) return;
    int s = ei[e];
    int d = ei[EE + e];
    int p = atomicAdd(&g_cnt[d], 1);
    if (p < CAP) g_bucket[d * CAP + p] = s;
}

// ---------------- GEMM1: h' = dinv .* (x @ W_gcn) -----------------------------
__global__ void __launch_bounds__(256, 4) k_gemm1(const float* __restrict__ x,
                                                  const float* __restrict__ W) {
    __shared__ float4 xs4[64 * CV];
    const int tid = threadIdx.x;
    const int tx  = tid & 31;
    const int ty  = tid >> 5;
    const int row0 = blockIdx.x * 64;

    const float4* x4 = (const float4*)x;
    #pragma unroll
    for (int j = 0; j < 8; ++j) {
        int idx = tid + j * 256;
        int gr = row0 + (idx >> 5);
        xs4[idx] = (gr < NN) ? x4[gr * CV + (idx & 31)]
                             : make_float4(0.f, 0.f, 0.f, 0.f);
    }
    __syncthreads();

    float4 acc[8];
    #pragma unroll
    for (int i = 0; i < 8; ++i) acc[i] = make_float4(0.f, 0.f, 0.f, 0.f);

    const float4* W4 = (const float4*)W;
    #pragma unroll 2
    for (int kk = 0; kk < 32; ++kk) {
        {   // k = 4kk+0, 4kk+1
            float4 b0 = __ldg(&W4[(4 * kk + 0) * CV + tx]);
            float4 b1 = __ldg(&W4[(4 * kk + 1) * CV + tx]);
            #pragma unroll
            for (int i = 0; i < 8; ++i) {
                float4 a = xs4[(ty * 8 + i) * CV + kk];
                acc[i].x = fmaf(a.x, b0.x, acc[i].x);
                acc[i].y = fmaf(a.x, b0.y, acc[i].y);
                acc[i].z = fmaf(a.x, b0.z, acc[i].z);
                acc[i].w = fmaf(a.x, b0.w, acc[i].w);
                acc[i].x = fmaf(a.y, b1.x, acc[i].x);
                acc[i].y = fmaf(a.y, b1.y, acc[i].y);
                acc[i].z = fmaf(a.y, b1.z, acc[i].z);
                acc[i].w = fmaf(a.y, b1.w, acc[i].w);
            }
        }
        {   // k = 4kk+2, 4kk+3
            float4 b2 = __ldg(&W4[(4 * kk + 2) * CV + tx]);
            float4 b3 = __ldg(&W4[(4 * kk + 3) * CV + tx]);
            #pragma unroll
            for (int i = 0; i < 8; ++i) {
                float4 a = xs4[(ty * 8 + i) * CV + kk];
                acc[i].x = fmaf(a.z, b2.x, acc[i].x);
                acc[i].y = fmaf(a.z, b2.y, acc[i].y);
                acc[i].z = fmaf(a.z, b2.z, acc[i].z);
                acc[i].w = fmaf(a.z, b2.w, acc[i].w);
                acc[i].x = fmaf(a.w, b3.x, acc[i].x);
                acc[i].y = fmaf(a.w, b3.y, acc[i].y);
                acc[i].z = fmaf(a.w, b3.z, acc[i].z);
                acc[i].w = fmaf(a.w, b3.w, acc[i].w);
            }
        }
    }

    #pragma unroll
    for (int i = 0; i < 8; ++i) {
        int r = row0 + ty * 8 + i;
        if (r < NN) {
            float dv = rsqrtf((float)(g_cnt[r] + 1));   // true degree + self-loop
            float4 v = acc[i];
            v.x *= dv; v.y *= dv; v.z *= dv; v.w *= dv;
            g_h[r * CV + tx] = v;
        }
    }
}

// ---------------- fused gather + MLP -------------------------------------------
// agg[d] = relu( dinv[d] * (h'[d] + sum_{s in N(d)} h'[s]) + b_gcn )
// then block GEMM with W1 and W2 epilogue.
__global__ void __launch_bounds__(256, 4) k_gmlp(const float* __restrict__ bg,
                                                 const float* __restrict__ W1,
                                                 const float* __restrict__ b1,
                                                 const float* __restrict__ W2,
                                                 const float* __restrict__ b2,
                                                 float* __restrict__ out) {
    __shared__ float4 as4[64 * CV];
    const int tid  = threadIdx.x;
    const int lane = tid & 31;
    const int ty   = tid >> 5;        // warp id 0..7
    const int row0 = blockIdx.x * 64;

    const float4 bgv = __ldg(&((const float4*)bg)[lane]);

    // ---- gather: warp ty handles nodes row0 + ty*8 + i ----
    #pragma unroll 1
    for (int i = 0; i < 8; ++i) {
        int d = row0 + ty * 8 + i;
        float4 r;
        if (d < NN) {
            int deg = g_cnt[d];
            float dv_d = rsqrtf((float)(deg + 1));
            if (deg > CAP) deg = CAP;

            float4 a0 = g_h[d * CV + lane];      // self-loop term h'[d]
            float4 a1 = make_float4(0.f, 0.f, 0.f, 0.f);
            float4 a2 = make_float4(0.f, 0.f, 0.f, 0.f);
            float4 a3 = make_float4(0.f, 0.f, 0.f, 0.f);

            const int* bkt = &g_bucket[d * CAP];
            for (int j0 = 0; j0 < deg; j0 += 32) {
                int myi = j0 + lane;
                int s = (myi < deg) ? bkt[myi] : 0;
                int cnt = deg - j0; if (cnt > 32) cnt = 32;
                int t = 0;
                for (; t + 4 <= cnt; t += 4) {
                    int s0 = __shfl_sync(0xFFFFFFFFu, s, t);
                    int s1 = __shfl_sync(0xFFFFFFFFu, s, t + 1);
                    int s2 = __shfl_sync(0xFFFFFFFFu, s, t + 2);
                    int s3 = __shfl_sync(0xFFFFFFFFu, s, t + 3);
                    float4 v0 = g_h[s0 * CV + lane];
                    float4 v1 = g_h[s1 * CV + lane];
                    float4 v2 = g_h[s2 * CV + lane];
                    float4 v3 = g_h[s3 * CV + lane];
                    a0.x += v0.x; a0.y += v0.y; a0.z += v0.z; a0.w += v0.w;
                    a1.x += v1.x; a1.y += v1.y; a1.z += v1.z; a1.w += v1.w;
                    a2.x += v2.x; a2.y += v2.y; a2.z += v2.z; a2.w += v2.w;
                    a3.x += v3.x; a3.y += v3.y; a3.z += v3.z; a3.w += v3.w;
                }
                for (; t < cnt; ++t) {
                    int ss = __shfl_sync(0xFFFFFFFFu, s, t);
                    float4 v = g_h[ss * CV + lane];
                    a0.x += v.x; a0.y += v.y; a0.z += v.z; a0.w += v.w;
                }
            }
            a0.x += a1.x + a2.x + a3.x;
            a0.y += a1.y + a2.y + a3.y;
            a0.z += a1.z + a2.z + a3.z;
            a0.w += a1.w + a2.w + a3.w;
            r.x = fmaxf(fmaf(a0.x, dv_d, bgv.x), 0.f);
            r.y = fmaxf(fmaf(a0.y, dv_d, bgv.y), 0.f);
            r.z = fmaxf(fmaf(a0.z, dv_d, bgv.z), 0.f);
            r.w = fmaxf(fmaf(a0.w, dv_d, bgv.w), 0.f);
        } else {
            r = make_float4(0.f, 0.f, 0.f, 0.f);
        }
        as4[(ty * 8 + i) * CV + lane] = r;
    }
    __syncthreads();

    // ---- GEMM: tile64x128 @ W1, then W2 epilogue ----
    float4 acc[8];
    #pragma unroll
    for (int i = 0; i < 8; ++i) acc[i] = make_float4(0.f, 0.f, 0.f, 0.f);

    const float4* W14 = (const float4*)W1;
    #pragma unroll 2
    for (int kk = 0; kk < 32; ++kk) {
        {
            float4 b0 = __ldg(&W14[(4 * kk + 0) * CV + lane]);
            float4 b1v = __ldg(&W14[(4 * kk + 1) * CV + lane]);
            #pragma unroll
            for (int i = 0; i < 8; ++i) {
                float4 a = as4[(ty * 8 + i) * CV + kk];
                acc[i].x = fmaf(a.x, b0.x, acc[i].x);
                acc[i].y = fmaf(a.x, b0.y, acc[i].y);
                acc[i].z = fmaf(a.x, b0.z, acc[i].z);
                acc[i].w = fmaf(a.x, b0.w, acc[i].w);
                acc[i].x = fmaf(a.y, b1v.x, acc[i].x);
                acc[i].y = fmaf(a.y, b1v.y, acc[i].y);
                acc[i].z = fmaf(a.y, b1v.z, acc[i].z);
                acc[i].w = fmaf(a.y, b1v.w, acc[i].w);
            }
        }
        {
            float4 b2v = __ldg(&W14[(4 * kk + 2) * CV + lane]);
            float4 b3 = __ldg(&W14[(4 * kk + 3) * CV + lane]);
            #pragma unroll
            for (int i = 0; i < 8; ++i) {
                float4 a = as4[(ty * 8 + i) * CV + kk];
                acc[i].x = fmaf(a.z, b2v.x, acc[i].x);
                acc[i].y = fmaf(a.z, b2v.y, acc[i].y);
                acc[i].z = fmaf(a.z, b2v.z, acc[i].z);
                acc[i].w = fmaf(a.z, b2v.w, acc[i].w);
                acc[i].x = fmaf(a.w, b3.x, acc[i].x);
                acc[i].y = fmaf(a.w, b3.y, acc[i].y);
                acc[i].z = fmaf(a.w, b3.z, acc[i].z);
                acc[i].w = fmaf(a.w, b3.w, acc[i].w);
            }
        }
    }

    float4 b1r = __ldg(&((const float4*)b1)[lane]);
    float4 w2r = __ldg(&((const float4*)W2)[lane]);
    float  b2s = __ldg(b2);

    #pragma unroll
    for (int i = 0; i < 8; ++i) {
        int r = row0 + ty * 8 + i;
        float h0 = fmaxf(acc[i].x + b1r.x, 0.f);
        float h1 = fmaxf(acc[i].y + b1r.y, 0.f);
        float h2 = fmaxf(acc[i].z + b1r.z, 0.f);
        float h3 = fmaxf(acc[i].w + b1r.w, 0.f);
        float pd = h0 * w2r.x + h1 * w2r.y + h2 * w2r.z + h3 * w2r.w;
        #pragma unroll
        for (int off = 16; off > 0; off >>= 1)
            pd += __shfl_down_sync(0xFFFFFFFFu, pd, off);
        if (lane == 0 && r < NN) out[r] = pd + b2s;
    }
}

// ---------------- launch --------------------------------------------------------
extern "C" void kernel_launch(void* const* d_in, const int* in_sizes, int n_in,
                              void* d_out, int out_size) {
    const float* x  = (const float*)d_in[0];
    const int*   ei = (const int*)  d_in[1];
    const float* Wg = (const float*)d_in[2];
    const float* bg = (const float*)d_in[3];
    const float* W1 = (const float*)d_in[4];
    const float* b1 = (const float*)d_in[5];
    const float* W2 = (const float*)d_in[6];
    const float* b2 = (const float*)d_in[7];
    float* out = (float*)d_out;

    k_init <<<(NN + 255) / 256, 256>>>();
    k_fill <<<(EE + 255) / 256, 256>>>(ei);
    k_gemm1<<<(NN + 63) / 64, 256>>>(x, Wg);
    k_gmlp <<<(NN + 63) / 64, 256>>>(bg, W1, b1, W2, b2, out);
}

// round 5
// speedup vs baseline: 1.9836x; 1.9836x over previous
#include <cuda_runtime.h>

#define NN 50000
#define EE 800000
#define CC 128
#define CV 32            // CC/4 float4 per row
#define CAP 128          // deg ~ Poisson(16), max ~50 << 128

// ---------------- scratch (device globals; no allocation allowed) -----------
__device__ int    g_cnt[NN];          // edge in-degree (== fill cursor)
__device__ float4 g_h[NN * CV];       // h' = dinv * (x @ W_gcn)   (25.6 MB)
__device__ int    g_bucket[NN * CAP]; // src ids grouped by dst    (25.6 MB)

// ---------------- bucket build ------------------------------------------------
__global__ void k_init() {
    int i = blockIdx.x * blockDim.x + threadIdx.x;
    if (i < NN) g_cnt[i] = 0;
}

__global__ void k_fill(const int* __restrict__ ei) {
    int e = blockIdx.x * blockDim.x + threadIdx.x;
    if (e >= EE) return;
    int s = ei[e];
    int d = ei[EE + e];
    int p = atomicAdd(&g_cnt[d], 1);
    if (p < CAP) g_bucket[d * CAP + p] = s;
}

// ---------------- GEMM1: h' = dinv .* (x @ W_gcn) -----------------------------
__global__ void __launch_bounds__(256) k_gemm1(const float* __restrict__ x,
                                               const float* __restrict__ W) {
    __shared__ float4 xs4[64 * CV];
    const int tid = threadIdx.x;
    const int tx  = tid & 31;
    const int ty  = tid >> 5;
    const int row0 = blockIdx.x * 64;

    const float4* x4 = (const float4*)x;
    #pragma unroll
    for (int j = 0; j < 8; ++j) {
        int idx = tid + j * 256;
        int gr = row0 + (idx >> 5);
        xs4[idx] = (gr < NN) ? x4[gr * CV + (idx & 31)]
                             : make_float4(0.f, 0.f, 0.f, 0.f);
    }
    __syncthreads();

    float4 acc[8];
    #pragma unroll
    for (int i = 0; i < 8; ++i) acc[i] = make_float4(0.f, 0.f, 0.f, 0.f);

    const float4* W4 = (const float4*)W;
    #pragma unroll 2
    for (int kk = 0; kk < 32; ++kk) {
        float4 b0 = __ldg(&W4[(4 * kk + 0) * CV + tx]);
        float4 b1 = __ldg(&W4[(4 * kk + 1) * CV + tx]);
        float4 b2 = __ldg(&W4[(4 * kk + 2) * CV + tx]);
        float4 b3 = __ldg(&W4[(4 * kk + 3) * CV + tx]);
        #pragma unroll
        for (int i = 0; i < 8; ++i) {
            float4 a = xs4[(ty * 8 + i) * CV + kk];
            acc[i].x = fmaf(a.x, b0.x, acc[i].x);
            acc[i].y = fmaf(a.x, b0.y, acc[i].y);
            acc[i].z = fmaf(a.x, b0.z, acc[i].z);
            acc[i].w = fmaf(a.x, b0.w, acc[i].w);
            acc[i].x = fmaf(a.y, b1.x, acc[i].x);
            acc[i].y = fmaf(a.y, b1.y, acc[i].y);
            acc[i].z = fmaf(a.y, b1.z, acc[i].z);
            acc[i].w = fmaf(a.y, b1.w, acc[i].w);
            acc[i].x = fmaf(a.z, b2.x, acc[i].x);
            acc[i].y = fmaf(a.z, b2.y, acc[i].y);
            acc[i].z = fmaf(a.z, b2.z, acc[i].z);
            acc[i].w = fmaf(a.z, b2.w, acc[i].w);
            acc[i].x = fmaf(a.w, b3.x, acc[i].x);
            acc[i].y = fmaf(a.w, b3.y, acc[i].y);
            acc[i].z = fmaf(a.w, b3.z, acc[i].z);
            acc[i].w = fmaf(a.w, b3.w, acc[i].w);
        }
    }

    #pragma unroll
    for (int i = 0; i < 8; ++i) {
        int r = row0 + ty * 8 + i;
        if (r < NN) {
            float dv = rsqrtf((float)(g_cnt[r] + 1));   // degree + self-loop
            float4 v = acc[i];
            v.x *= dv; v.y *= dv; v.z *= dv; v.w *= dv;
            g_h[r * CV + tx] = v;
        }
    }
}

// ---------------- fused gather + MLP -------------------------------------------
// agg[d] = relu( dinv[d] * (h'[d] + sum_{s in N(d)} h'[s]) + b_gcn )
// then block GEMM with W1 and W2 epilogue.
__global__ void __launch_bounds__(256) k_gmlp(const float* __restrict__ bg,
                                              const float* __restrict__ W1,
                                              const float* __restrict__ b1,
                                              const float* __restrict__ W2,
                                              const float* __restrict__ b2,
                                              float* __restrict__ out) {
    __shared__ float4 as4[64 * CV];
    const int tid  = threadIdx.x;
    const int lane = tid & 31;
    const int ty   = tid >> 5;        // warp id 0..7
    const int row0 = blockIdx.x * 64;

    const float4 bgv = __ldg(&((const float4*)bg)[lane]);

    // ---- gather: warp ty handles nodes row0 + ty*8 + i ----
    #pragma unroll 1
    for (int i = 0; i < 8; ++i) {
        int d = row0 + ty * 8 + i;
        float4 r;
        if (d < NN) {
            int deg = g_cnt[d];
            float dv_d = rsqrtf((float)(deg + 1));
            if (deg > CAP) deg = CAP;

            float4 a0 = g_h[d * CV + lane];      // self-loop term h'[d]
            float4 a1 = make_float4(0.f, 0.f, 0.f, 0.f);

            const int* bkt = &g_bucket[d * CAP];
            #pragma unroll 1
            for (int j0 = 0; j0 < deg; j0 += 32) {
                int myi = j0 + lane;
                int s = (myi < deg) ? bkt[myi] : 0;
                int cnt = deg - j0; if (cnt > 32) cnt = 32;
                int t = 0;
                #pragma unroll 1
                for (; t + 4 <= cnt; t += 4) {
                    int s0 = __shfl_sync(0xFFFFFFFFu, s, t);
                    int s1 = __shfl_sync(0xFFFFFFFFu, s, t + 1);
                    int s2 = __shfl_sync(0xFFFFFFFFu, s, t + 2);
                    int s3 = __shfl_sync(0xFFFFFFFFu, s, t + 3);
                    float4 v0 = g_h[s0 * CV + lane];
                    float4 v1 = g_h[s1 * CV + lane];
                    float4 v2 = g_h[s2 * CV + lane];
                    float4 v3 = g_h[s3 * CV + lane];
                    a0.x += v0.x; a0.y += v0.y; a0.z += v0.z; a0.w += v0.w;
                    a1.x += v1.x; a1.y += v1.y; a1.z += v1.z; a1.w += v1.w;
                    a0.x += v2.x; a0.y += v2.y; a0.z += v2.z; a0.w += v2.w;
                    a1.x += v3.x; a1.y += v3.y; a1.z += v3.z; a1.w += v3.w;
                }
                #pragma unroll 1
                for (; t < cnt; ++t) {
                    int ss = __shfl_sync(0xFFFFFFFFu, s, t);
                    float4 v = g_h[ss * CV + lane];
                    a0.x += v.x; a0.y += v.y; a0.z += v.z; a0.w += v.w;
                }
            }
            a0.x += a1.x; a0.y += a1.y; a0.z += a1.z; a0.w += a1.w;
            r.x = fmaxf(fmaf(a0.x, dv_d, bgv.x), 0.f);
            r.y = fmaxf(fmaf(a0.y, dv_d, bgv.y), 0.f);
            r.z = fmaxf(fmaf(a0.z, dv_d, bgv.z), 0.f);
            r.w = fmaxf(fmaf(a0.w, dv_d, bgv.w), 0.f);
        } else {
            r = make_float4(0.f, 0.f, 0.f, 0.f);
        }
        as4[(ty * 8 + i) * CV + lane] = r;
    }
    __syncthreads();

    // ---- GEMM: tile64x128 @ W1, then W2 epilogue ----
    float4 acc[8];
    #pragma unroll
    for (int i = 0; i < 8; ++i) acc[i] = make_float4(0.f, 0.f, 0.f, 0.f);

    const float4* W14 = (const float4*)W1;
    #pragma unroll 2
    for (int kk = 0; kk < 32; ++kk) {
        float4 b0 = __ldg(&W14[(4 * kk + 0) * CV + lane]);
        float4 b1v = __ldg(&W14[(4 * kk + 1) * CV + lane]);
        float4 b2v = __ldg(&W14[(4 * kk + 2) * CV + lane]);
        float4 b3 = __ldg(&W14[(4 * kk + 3) * CV + lane]);
        #pragma unroll
        for (int i = 0; i < 8; ++i) {
            float4 a = as4[(ty * 8 + i) * CV + kk];
            acc[i].x = fmaf(a.x, b0.x, acc[i].x);
            acc[i].y = fmaf(a.x, b0.y, acc[i].y);
            acc[i].z = fmaf(a.x, b0.z, acc[i].z);
            acc[i].w = fmaf(a.x, b0.w, acc[i].w);
            acc[i].x = fmaf(a.y, b1v.x, acc[i].x);
            acc[i].y = fmaf(a.y, b1v.y, acc[i].y);
            acc[i].z = fmaf(a.y, b1v.z, acc[i].z);
            acc[i].w = fmaf(a.y, b1v.w, acc[i].w);
            acc[i].x = fmaf(a.z, b2v.x, acc[i].x);
            acc[i].y = fmaf(a.z, b2v.y, acc[i].y);
            acc[i].z = fmaf(a.z, b2v.z, acc[i].z);
            acc[i].w = fmaf(a.z, b2v.w, acc[i].w);
            acc[i].x = fmaf(a.w, b3.x, acc[i].x);
            acc[i].y = fmaf(a.w, b3.y, acc[i].y);
            acc[i].z = fmaf(a.w, b3.z, acc[i].z);
            acc[i].w = fmaf(a.w, b3.w, acc[i].w);
        }
    }

    float4 b1r = __ldg(&((const float4*)b1)[lane]);
    float4 w2r = __ldg(&((const float4*)W2)[lane]);
    float  b2s = __ldg(b2);

    #pragma unroll
    for (int i = 0; i < 8; ++i) {
        int r = row0 + ty * 8 + i;
        float h0 = fmaxf(acc[i].x + b1r.x, 0.f);
        float h1 = fmaxf(acc[i].y + b1r.y, 0.f);
        float h2 = fmaxf(acc[i].z + b1r.z, 0.f);
        float h3 = fmaxf(acc[i].w + b1r.w, 0.f);
        float pd = h0 * w2r.x + h1 * w2r.y + h2 * w2r.z + h3 * w2r.w;
        #pragma unroll
        for (int off = 16; off > 0; off >>= 1)
            pd += __shfl_down_sync(0xFFFFFFFFu, pd, off);
        if (lane == 0 && r < NN) out[r] = pd + b2s;
    }
}

// ---------------- launch --------------------------------------------------------
extern "C" void kernel_launch(void* const* d_in, const int* in_sizes, int n_in,
                              void* d_out, int out_size) {
    const float* x  = (const float*)d_in[0];
    const int*   ei = (const int*)  d_in[1];
    const float* Wg = (const float*)d_in[2];
    const float* bg = (const float*)d_in[3];
    const float* W1 = (const float*)d_in[4];
    const float* b1 = (const float*)d_in[5];
    const float* W2 = (const float*)d_in[6];
    const float* b2 = (const float*)d_in[7];
    float* out = (float*)d_out;

    k_init <<<(NN + 255) / 256, 256>>>();
    k_fill <<<(EE + 255) / 256, 256>>>(ei);
    k_gemm1<<<(NN + 63) / 64, 256>>>(x, Wg);
    k_gmlp <<<(NN + 63) / 64, 256>>>(bg, W1, b1, W2, b2, out);
}

// round 6
// speedup vs baseline: 2.1248x; 1.0712x over previous
#include <cuda_runtime.h>

#define NN 50000
#define EE 800000
#define CC 128
#define CV 32            // CC/4 float4 per row
#define CAP 128          // deg ~ Poisson(16), max ~50 << 128

// ---------------- scratch (device globals; no allocation allowed) -----------
__device__ int    g_cnt[NN];          // edge in-degree (== fill cursor)
__device__ float4 g_h[NN * CV];       // h' = dinv * (x @ W_gcn)   (25.6 MB)
__device__ float4 g_agg[NN * CV];     // relu(agg + b_gcn)         (25.6 MB)
__device__ int    g_bucket[NN * CAP]; // src ids grouped by dst    (25.6 MB)

// ---------------- packed f32x2 helpers (sm_103a FFMA2) ----------------------
__device__ __forceinline__ unsigned long long pk2(float lo, float hi) {
    unsigned long long r;
    asm("mov.b64 %0, {%1, %2};" : "=l"(r) : "f"(lo), "f"(hi));
    return r;
}
__device__ __forceinline__ void upk2(unsigned long long v, float& lo, float& hi) {
    asm("mov.b64 {%0, %1}, %2;" : "=f"(lo), "=f"(hi) : "l"(v));
}
__device__ __forceinline__ void ffma2(unsigned long long& d,
                                      unsigned long long a,
                                      unsigned long long b) {
    asm("fma.rn.f32x2 %0, %1, %2, %0;" : "+l"(d) : "l"(a), "l"(b));
}

// ---------------- bucket build ------------------------------------------------
__global__ void k_init() {
    int i = blockIdx.x * blockDim.x + threadIdx.x;
    if (i < NN) g_cnt[i] = 0;
}

__global__ void k_fill(const int* __restrict__ ei) {
    int e4 = blockIdx.x * blockDim.x + threadIdx.x;
    if (e4 >= EE / 4) return;
    int4 s = ((const int4*)ei)[e4];
    int4 d = ((const int4*)(ei + EE))[e4];
    int p;
    p = atomicAdd(&g_cnt[d.x], 1); if (p < CAP) g_bucket[d.x * CAP + p] = s.x;
    p = atomicAdd(&g_cnt[d.y], 1); if (p < CAP) g_bucket[d.y * CAP + p] = s.y;
    p = atomicAdd(&g_cnt[d.z], 1); if (p < CAP) g_bucket[d.z * CAP + p] = s.z;
    p = atomicAdd(&g_cnt[d.w], 1); if (p < CAP) g_bucket[d.w * CAP + p] = s.w;
}

// ---------------- GEMM1: h' = dinv .* (x @ W_gcn) -----------------------------
__global__ void __launch_bounds__(256) k_gemm1(const float* __restrict__ x,
                                               const float* __restrict__ W) {
    __shared__ float4 xs4[64 * CV];
    const int tid = threadIdx.x;
    const int tx  = tid & 31;
    const int ty  = tid >> 5;
    const int row0 = blockIdx.x * 64;

    const float4* x4 = (const float4*)x;
    #pragma unroll
    for (int j = 0; j < 8; ++j) {
        int idx = tid + j * 256;
        int gr = row0 + (idx >> 5);
        xs4[idx] = (gr < NN) ? x4[gr * CV + (idx & 31)]
                             : make_float4(0.f, 0.f, 0.f, 0.f);
    }
    __syncthreads();

    unsigned long long acc2[8][2];   // [i][0]=cols(0,1)  [i][1]=cols(2,3)
    #pragma unroll
    for (int i = 0; i < 8; ++i) { acc2[i][0] = 0ull; acc2[i][1] = 0ull; }

    const float4* W4 = (const float4*)W;
    #pragma unroll 2
    for (int kk = 0; kk < 32; ++kk) {
        float4 b0 = __ldg(&W4[(4 * kk + 0) * CV + tx]);
        float4 b1 = __ldg(&W4[(4 * kk + 1) * CV + tx]);
        float4 b2 = __ldg(&W4[(4 * kk + 2) * CV + tx]);
        float4 b3 = __ldg(&W4[(4 * kk + 3) * CV + tx]);
        unsigned long long B0l = pk2(b0.x, b0.y), B0h = pk2(b0.z, b0.w);
        unsigned long long B1l = pk2(b1.x, b1.y), B1h = pk2(b1.z, b1.w);
        unsigned long long B2l = pk2(b2.x, b2.y), B2h = pk2(b2.z, b2.w);
        unsigned long long B3l = pk2(b3.x, b3.y), B3h = pk2(b3.z, b3.w);
        #pragma unroll
        for (int i = 0; i < 8; ++i) {
            float4 a = xs4[(ty * 8 + i) * CV + kk];
            unsigned long long ax = pk2(a.x, a.x);
            unsigned long long ay = pk2(a.y, a.y);
            unsigned long long az = pk2(a.z, a.z);
            unsigned long long aw = pk2(a.w, a.w);
            ffma2(acc2[i][0], ax, B0l); ffma2(acc2[i][1], ax, B0h);
            ffma2(acc2[i][0], ay, B1l); ffma2(acc2[i][1], ay, B1h);
            ffma2(acc2[i][0], az, B2l); ffma2(acc2[i][1], az, B2h);
            ffma2(acc2[i][0], aw, B3l); ffma2(acc2[i][1], aw, B3h);
        }
    }

    #pragma unroll
    for (int i = 0; i < 8; ++i) {
        int r = row0 + ty * 8 + i;
        if (r < NN) {
            float dv = rsqrtf((float)(g_cnt[r] + 1));   // degree + self-loop
            float4 v;
            upk2(acc2[i][0], v.x, v.y);
            upk2(acc2[i][1], v.z, v.w);
            v.x *= dv; v.y *= dv; v.z *= dv; v.w *= dv;
            g_h[r * CV + tx] = v;
        }
    }
}

// ---------------- gather: agg[d] = relu(dinv_d*(h'[d]+sum h'[s]) + bg) --------
// One warp per dst node, lean registers for high occupancy (L2-latency bound).
__global__ void __launch_bounds__(256) k_gather(const float* __restrict__ bg) {
    int gw   = (blockIdx.x * blockDim.x + threadIdx.x) >> 5;
    int lane = threadIdx.x & 31;
    if (gw >= NN) return;
    const int d = gw;

    int deg = g_cnt[d];
    float dv_d = rsqrtf((float)(deg + 1));
    if (deg > CAP) deg = CAP;

    float4 a0 = g_h[d * CV + lane];      // self-loop term
    float4 a1 = make_float4(0.f, 0.f, 0.f, 0.f);

    const int* bkt = &g_bucket[d * CAP];
    for (int j0 = 0; j0 < deg; j0 += 32) {
        int myi = j0 + lane;
        int s = (myi < deg) ? bkt[myi] : 0;
        int cnt = deg - j0; if (cnt > 32) cnt = 32;
        int t = 0;
        for (; t + 4 <= cnt; t += 4) {
            int s0 = __shfl_sync(0xFFFFFFFFu, s, t);
            int s1 = __shfl_sync(0xFFFFFFFFu, s, t + 1);
            int s2 = __shfl_sync(0xFFFFFFFFu, s, t + 2);
            int s3 = __shfl_sync(0xFFFFFFFFu, s, t + 3);
            float4 v0 = g_h[s0 * CV + lane];
            float4 v1 = g_h[s1 * CV + lane];
            float4 v2 = g_h[s2 * CV + lane];
            float4 v3 = g_h[s3 * CV + lane];
            a0.x += v0.x; a0.y += v0.y; a0.z += v0.z; a0.w += v0.w;
            a1.x += v1.x; a1.y += v1.y; a1.z += v1.z; a1.w += v1.w;
            a0.x += v2.x; a0.y += v2.y; a0.z += v2.z; a0.w += v2.w;
            a1.x += v3.x; a1.y += v3.y; a1.z += v3.z; a1.w += v3.w;
        }
        for (; t < cnt; ++t) {
            int ss = __shfl_sync(0xFFFFFFFFu, s, t);
            float4 v = g_h[ss * CV + lane];
            a0.x += v.x; a0.y += v.y; a0.z += v.z; a0.w += v.w;
        }
    }
    a0.x += a1.x; a0.y += a1.y; a0.z += a1.z; a0.w += a1.w;

    float4 bgv = __ldg(&((const float4*)bg)[lane]);
    float4 r;
    r.x = fmaxf(fmaf(a0.x, dv_d, bgv.x), 0.f);
    r.y = fmaxf(fmaf(a0.y, dv_d, bgv.y), 0.f);
    r.z = fmaxf(fmaf(a0.z, dv_d, bgv.z), 0.f);
    r.w = fmaxf(fmaf(a0.w, dv_d, bgv.w), 0.f);
    g_agg[d * CV + lane] = r;
}

// ---------------- MLP: out = relu(a @ W1 + b1) @ W2 + b2 ----------------------
__global__ void __launch_bounds__(256) k_mlp(const float* __restrict__ W1,
                                             const float* __restrict__ b1,
                                             const float* __restrict__ W2,
                                             const float* __restrict__ b2,
                                             float* __restrict__ out) {
    __shared__ float4 as4[64 * CV];
    const int tid  = threadIdx.x;
    const int lane = tid & 31;
    const int ty   = tid >> 5;
    const int row0 = blockIdx.x * 64;

    #pragma unroll
    for (int j = 0; j < 8; ++j) {
        int idx = tid + j * 256;
        int gr = row0 + (idx >> 5);
        as4[idx] = (gr < NN) ? g_agg[gr * CV + (idx & 31)]
                             : make_float4(0.f, 0.f, 0.f, 0.f);
    }
    __syncthreads();

    unsigned long long acc2[8][2];
    #pragma unroll
    for (int i = 0; i < 8; ++i) { acc2[i][0] = 0ull; acc2[i][1] = 0ull; }

    const float4* W14 = (const float4*)W1;
    #pragma unroll 2
    for (int kk = 0; kk < 32; ++kk) {
        float4 b0 = __ldg(&W14[(4 * kk + 0) * CV + lane]);
        float4 b1v = __ldg(&W14[(4 * kk + 1) * CV + lane]);
        float4 b2v = __ldg(&W14[(4 * kk + 2) * CV + lane]);
        float4 b3 = __ldg(&W14[(4 * kk + 3) * CV + lane]);
        unsigned long long B0l = pk2(b0.x, b0.y),  B0h = pk2(b0.z, b0.w);
        unsigned long long B1l = pk2(b1v.x, b1v.y), B1h = pk2(b1v.z, b1v.w);
        unsigned long long B2l = pk2(b2v.x, b2v.y), B2h = pk2(b2v.z, b2v.w);
        unsigned long long B3l = pk2(b3.x, b3.y),  B3h = pk2(b3.z, b3.w);
        #pragma unroll
        for (int i = 0; i < 8; ++i) {
            float4 a = as4[(ty * 8 + i) * CV + kk];
            unsigned long long ax = pk2(a.x, a.x);
            unsigned long long ay = pk2(a.y, a.y);
            unsigned long long az = pk2(a.z, a.z);
            unsigned long long aw = pk2(a.w, a.w);
            ffma2(acc2[i][0], ax, B0l); ffma2(acc2[i][1], ax, B0h);
            ffma2(acc2[i][0], ay, B1l); ffma2(acc2[i][1], ay, B1h);
            ffma2(acc2[i][0], az, B2l); ffma2(acc2[i][1], az, B2h);
            ffma2(acc2[i][0], aw, B3l); ffma2(acc2[i][1], aw, B3h);
        }
    }

    float4 b1r = __ldg(&((const float4*)b1)[lane]);
    float4 w2r = __ldg(&((const float4*)W2)[lane]);
    float  b2s = __ldg(b2);

    #pragma unroll
    for (int i = 0; i < 8; ++i) {
        int r = row0 + ty * 8 + i;
        float4 c;
        upk2(acc2[i][0], c.x, c.y);
        upk2(acc2[i][1], c.z, c.w);
        float h0 = fmaxf(c.x + b1r.x, 0.f);
        float h1 = fmaxf(c.y + b1r.y, 0.f);
        float h2 = fmaxf(c.z + b1r.z, 0.f);
        float h3 = fmaxf(c.w + b1r.w, 0.f);
        float pd = h0 * w2r.x + h1 * w2r.y + h2 * w2r.z + h3 * w2r.w;
        #pragma unroll
        for (int off = 16; off > 0; off >>= 1)
            pd += __shfl_down_sync(0xFFFFFFFFu, pd, off);
        if (lane == 0 && r < NN) out[r] = pd + b2s;
    }
}

// ---------------- launch --------------------------------------------------------
extern "C" void kernel_launch(void* const* d_in, const int* in_sizes, int n_in,
                              void* d_out, int out_size) {
    const float* x  = (const float*)d_in[0];
    const int*   ei = (const int*)  d_in[1];
    const float* Wg = (const float*)d_in[2];
    const float* bg = (const float*)d_in[3];
    const float* W1 = (const float*)d_in[4];
    const float* b1 = (const float*)d_in[5];
    const float* W2 = (const float*)d_in[6];
    const float* b2 = (const float*)d_in[7];
    float* out = (float*)d_out;

    k_init  <<<(NN + 255) / 256, 256>>>();
    k_fill  <<<(EE / 4 + 255) / 256, 256>>>(ei);
    k_gemm1 <<<(NN + 63) / 64, 256>>>(x, Wg);
    k_gather<<<(NN * 32 + 255) / 256, 256>>>(bg);
    k_mlp   <<<(NN + 63) / 64, 256>>>(W1, b1, W2, b2, out);
}